// round 7
// baseline (speedup 1.0000x reference)
#include <cuda_runtime.h>
#include <cuda_bf16.h>
#include <math.h>
#include <stdint.h>

// Problem constants
#define BATCH 2
#define CDIM  192
#define C3    576
#define HDIM  256
#define WDIM  256
#define HWSZ  (HDIM*WDIM)       // 65536
#define HEADS 6
#define CHD   32
#define NWIN  2048
#define KD    192

#define NT     64               // px per tile
#define PXITER 8                // tiles per CTA
#define KSTEPS 12               // 192/16

// dynamic smem word offsets (uint32 words)
#define W_AHI 0
#define W_ALO 6144
#define W_BHI 12288
#define W_BLO 18432
#define SMEM_BYTES (24576 * 4)

typedef unsigned long long u64;

// ---------------- packed f32x2 helpers (k_attn) ----------------
__device__ __forceinline__ u64 pk1(float x) {
    u64 r; asm("mov.b64 %0,{%1,%1};" : "=l"(r) : "f"(x)); return r;
}
__device__ __forceinline__ void fma2(u64& d, u64 a, u64 b) {
    asm("fma.rn.f32x2 %0,%1,%2,%3;" : "=l"(d) : "l"(a), "l"(b), "l"(d));
}
__device__ __forceinline__ void mul2(u64& d, u64 a, u64 b) {
    asm("mul.rn.f32x2 %0,%1,%2;" : "=l"(d) : "l"(a), "l"(b));
}
__device__ __forceinline__ float2 up2(u64 v) {
    float2 f; asm("mov.b64 {%0,%1},%2;" : "=f"(f.x), "=f"(f.y) : "l"(v)); return f;
}

// ---------------- bf16 split helpers ----------------
__device__ __forceinline__ void split1(float x, uint32_t& h, uint32_t& l) {
    __nv_bfloat16 hb = __float2bfloat16(x);
    float r = x - __bfloat162float(hb);
    __nv_bfloat16 lb = __float2bfloat16(r);
    h = (uint32_t)__bfloat16_as_ushort(hb);
    l = (uint32_t)__bfloat16_as_ushort(lb);
}
// pack two floats -> (hiword, loword) bf16x2: low half = first element
__device__ __forceinline__ void split2(float a, float b, uint32_t& hw, uint32_t& lw) {
    uint32_t ha, la, hb2, lb2;
    split1(a, ha, la); split1(b, hb2, lb2);
    hw = ha | (hb2 << 16);
    lw = la | (lb2 << 16);
}

// mma.sync m16n8k16 bf16, fp32 accumulate (portable PTX, sm_80+)
__device__ __forceinline__ void mma16816(float* c, const uint32_t* a, const uint32_t* b) {
    asm volatile(
        "mma.sync.aligned.m16n8k16.row.col.f32.bf16.bf16.f32 "
        "{%0,%1,%2,%3},{%4,%5,%6,%7},{%8,%9},{%0,%1,%2,%3};"
        : "+f"(c[0]), "+f"(c[1]), "+f"(c[2]), "+f"(c[3])
        : "r"(a[0]), "r"(a[1]), "r"(a[2]), "r"(a[3]), "r"(b[0]), "r"(b[1]));
}

// Scratch (device globals; no allocation allowed)
__device__ float g_qkv[(size_t)BATCH*C3*HWSZ];
__device__ float g_dw [(size_t)BATCH*C3*HWSZ];
__device__ float g_t  [(size_t)BATCH*CDIM*HWSZ];

// ---------------------------------------------------------------------------
// K1/K4: split-bf16 tensor-core GEMM via mma.sync.
// Y[b,m,hw] = sum_k W[m,k] * X[b,k,hw] (+ bias[m])
// CTA: 128 threads / 4 warps (2x2), tile 64M x 64N, full K=192 in smem.
// 3 passes: Whi*Xhi + Whi*Xlo + Wlo*Xhi.
//
// A smem layout: word(ks, lh, m, tg) = ks*512 + lh*256 + m*4 + tg
//   holds bf16x2 of W[m0+m][k], k = ks*16 + lh*8 + tg*2 (+1)
//   fragment loads: bank = (m*4+tg)%32 = lane -> conflict-free.
// B smem layout: word(frag, ks, k2, nw) = frag*768 + ks*64 + k2*8 + nw
//   holds bf16x2 of X[k][px], k = ks*16 + k2*2 (+1), px = hw0 + frag*8 + nw
//   fragment loads: bank = (k2*8+nw) -> conflict-free.
// ---------------------------------------------------------------------------
__global__ __launch_bounds__(128) void k_gemm_mma(
    const float* __restrict__ W, const float* __restrict__ X,
    float* __restrict__ Y, const float* __restrict__ bias,
    int hasBias, int Mtot)
{
    extern __shared__ uint32_t sm[];
    int tid = threadIdx.x;
    int lane = tid & 31, wid = tid >> 5;
    int g  = lane >> 2, tg = lane & 3;
    int warp_m = wid >> 1, warp_n = wid & 1;
    int m0 = blockIdx.y * 64;

    // ---- stage A (weights) once: 64 rows x 192 k, hi+lo ----
    for (int u = tid; u < 64 * 48; u += 128) {
        int r = u / 48, q = u % 48;          // q: float4 index along k
        int k = q * 4;
        float4 v = *(const float4*)(W + (size_t)(m0 + r) * KD + k);
        uint32_t h0, l0, h1, l1;
        split2(v.x, v.y, h0, l0);
        split2(v.z, v.w, h1, l1);
        int ks = k >> 4, lh = (k >> 3) & 1, tgw = (k >> 1) & 3;  // tgw in {0,2}
        int idx = ks * 512 + lh * 256 + r * 4 + tgw;
        sm[W_AHI + idx] = h0; sm[W_AHI + idx + 1] = h1;
        sm[W_ALO + idx] = l0; sm[W_ALO + idx + 1] = l1;
    }

    // bias per output row (constant across iterations)
    float bv[2][2] = {{0.f,0.f},{0.f,0.f}};
    if (hasBias) {
        #pragma unroll
        for (int mf = 0; mf < 2; mf++) {
            int row = m0 + warp_m * 32 + mf * 16 + g;
            bv[mf][0] = bias[row];
            bv[mf][1] = bias[row + 8];
        }
    }

    for (int it = 0; it < PXITER; ++it) {
        int gp = (blockIdx.x * PXITER + it) * NT;
        int b = gp / HWSZ, hw0 = gp % HWSZ;
        const float* Xb = X + (size_t)b * KD * HWSZ + hw0;
        __syncthreads();   // previous iter reads done (also covers A stage on it=0)

        // ---- stage B: X[k][hw0..hw0+64), split hi/lo ----
        for (int u = tid; u < 1536; u += 128) {
            int k2 = u >> 4, p4 = (u & 15) * 4;
            int k = k2 * 2;
            float4 f0 = *(const float4*)(Xb + (size_t)k * HWSZ + p4);
            float4 f1 = *(const float4*)(Xb + (size_t)(k + 1) * HWSZ + p4);
            int ks = k2 >> 3, k2w = k2 & 7;
            const float a0[4] = {f0.x, f0.y, f0.z, f0.w};
            const float a1[4] = {f1.x, f1.y, f1.z, f1.w};
            #pragma unroll
            for (int j = 0; j < 4; j++) {
                int px = p4 + j;
                uint32_t hw_, lw_;
                split2(a0[j], a1[j], hw_, lw_);
                int idx = (px >> 3) * 768 + ks * 64 + k2w * 8 + (px & 7);
                sm[W_BHI + idx] = hw_;
                sm[W_BLO + idx] = lw_;
            }
        }
        __syncthreads();

        // ---- compute: 3 passes x 12 ksteps x (2 mf x 4 nf) mma ----
        float c[2][4][4];
        #pragma unroll
        for (int mf = 0; mf < 2; mf++)
            #pragma unroll
            for (int nf = 0; nf < 4; nf++)
                #pragma unroll
                for (int i = 0; i < 4; i++) c[mf][nf][i] = 0.f;

        #pragma unroll
        for (int pass = 0; pass < 3; pass++) {
            const uint32_t* A = sm + (pass == 2 ? W_ALO : W_AHI);
            const uint32_t* B = sm + (pass == 1 ? W_BLO : W_BHI);
            #pragma unroll 4
            for (int ks = 0; ks < KSTEPS; ks++) {
                uint32_t af[2][4];
                #pragma unroll
                for (int mf = 0; mf < 2; mf++) {
                    int mb = warp_m * 32 + mf * 16;
                    const uint32_t* Ak = A + ks * 512;
                    af[mf][0] = Ak[(mb + g) * 4 + tg];
                    af[mf][1] = Ak[(mb + 8 + g) * 4 + tg];
                    af[mf][2] = Ak[256 + (mb + g) * 4 + tg];
                    af[mf][3] = Ak[256 + (mb + 8 + g) * 4 + tg];
                }
                uint32_t bfr[4][2];
                #pragma unroll
                for (int nf = 0; nf < 4; nf++) {
                    const uint32_t* Bk = B + (warp_n * 4 + nf) * 768 + ks * 64;
                    bfr[nf][0] = Bk[tg * 8 + g];
                    bfr[nf][1] = Bk[(tg + 4) * 8 + g];
                }
                #pragma unroll
                for (int mf = 0; mf < 2; mf++)
                    #pragma unroll
                    for (int nf = 0; nf < 4; nf++)
                        mma16816(c[mf][nf], af[mf], bfr[nf]);
            }
        }

        // ---- epilogue: direct STG (each 4-lane group = one 32B sector) ----
        #pragma unroll
        for (int mf = 0; mf < 2; mf++) {
            int row0 = m0 + warp_m * 32 + mf * 16 + g;
            #pragma unroll
            for (int nf = 0; nf < 4; nf++) {
                int px = hw0 + warp_n * 32 + nf * 8 + tg * 2;
                float* d0 = Y + ((size_t)b * Mtot + row0) * HWSZ + px;
                float* d1 = Y + ((size_t)b * Mtot + row0 + 8) * HWSZ + px;
                *(float2*)d0 = make_float2(c[mf][nf][0] + bv[mf][0], c[mf][nf][1] + bv[mf][0]);
                *(float2*)d1 = make_float2(c[mf][nf][2] + bv[mf][1], c[mf][nf][3] + bv[mf][1]);
            }
        }
    }
}

// ---------------------------------------------------------------------------
// K2: depthwise 3x3, zero pad 1. float4 per thread (4 px). 128 thr = 2 rows.
// ---------------------------------------------------------------------------
__global__ __launch_bounds__(128) void k_dw(const float* __restrict__ w_dw)
{
    int tid = threadIdx.x;
    int ty = tid >> 6, tx = tid & 63;
    int y  = blockIdx.x * 2 + ty;
    int ch = blockIdx.y;
    int b  = blockIdx.z;
    int x0 = tx << 2;

    const float* wk = w_dw + ch * 9;
    size_t base = ((size_t)b * C3 + ch) * HWSZ;
    const float* src = g_qkv + base;

    float4 o = make_float4(0.f, 0.f, 0.f, 0.f);

    #pragma unroll
    for (int dy = -1; dy <= 1; dy++) {
        int yy = y + dy;
        if (yy < 0 || yy >= HDIM) continue;
        const float* row = src + (size_t)yy * WDIM + x0;
        float4 m = *(const float4*)row;
        float lft = (x0 > 0)   ? row[-1] : 0.f;
        float rgt = (x0 < 252) ? row[4]  : 0.f;
        float wl = wk[(dy+1)*3], wc = wk[(dy+1)*3+1], wr = wk[(dy+1)*3+2];
        o.x += wl*lft + wc*m.x + wr*m.y;
        o.y += wl*m.x + wc*m.y + wr*m.z;
        o.z += wl*m.y + wc*m.z + wr*m.w;
        o.w += wl*m.z + wc*m.w + wr*rgt;
    }
    *(float4*)(g_dw + base + (size_t)y * WDIM + x0) = o;
}

// ---------------------------------------------------------------------------
// K3: fused windowed channel attention per (window, head). f32x2 dots.
// ---------------------------------------------------------------------------
__global__ __launch_bounds__(128) void k_attn(
    const float* __restrict__ temp,
    const float* __restrict__ mlp_w,
    const float* __restrict__ mlp_b)
{
    __shared__ float sq[32 * 66];
    __shared__ float sk[32 * 66];
    __shared__ float sv[32 * 66];
    __shared__ float satt[32 * 33];
    __shared__ float sml[64 * 66];
    __shared__ float sb[64];

    int tid  = threadIdx.x;
    int wi   = blockIdx.x;
    int head = blockIdx.y;
    int b  = wi >> 10;
    int r  = wi & 1023;
    int h1 = r >> 5, w1 = r & 31;

    float tscale = temp[head];

    for (int i = tid; i < 1536; i += 128) {
        int z = i / 512;
        int rr = i - z * 512;
        int c  = rr >> 4;
        int q8 = rr & 15;
        int ty = q8 >> 1, half = q8 & 1;
        const float* gp = g_dw +
            (((size_t)(b * C3 + z * CDIM + head * CHD + c)) * HDIM + (h1*8 + ty)) * WDIM
            + w1 * 8 + half * 4;
        float4 v = *(const float4*)gp;
        float* s = (z == 0 ? sq : (z == 1 ? sk : sv)) + c * 66 + ty * 8 + half * 4;
        s[0] = v.x; s[1] = v.y; s[2] = v.z; s[3] = v.w;
    }
    for (int i = tid; i < 4096; i += 128)
        sml[(i >> 6) * 66 + (i & 63)] = mlp_w[i];
    if (tid < 64) sb[tid] = mlp_b[tid];
    __syncthreads();

    if (tid < 64) {
        float* row = (tid < 32) ? (sq + tid * 66) : (sk + (tid - 32) * 66);
        u64 s2 = 0ull;
        #pragma unroll
        for (int t = 0; t < 64; t += 2) {
            u64 v = *(const u64*)(row + t);
            fma2(s2, v, v);
        }
        float2 sp = up2(s2);
        float n = fmaxf(sqrtf(sp.x + sp.y), 1e-12f);
        u64 inv = pk1(1.f / n);
        #pragma unroll
        for (int t = 0; t < 64; t += 2) {
            u64 v = *(const u64*)(row + t);
            mul2(v, v, inv);
            *(u64*)(row + t) = v;
        }
    }
    __syncthreads();

    #pragma unroll
    for (int i = 0; i < 8; i++) {
        int e = tid + i * 128;
        int c = e >> 5, d = e & 31;
        const float* qr = sq + c * 66;
        const float* kr = sk + d * 66;
        u64 s2 = 0ull;
        #pragma unroll
        for (int t = 0; t < 64; t += 2)
            fma2(s2, *(const u64*)(qr + t), *(const u64*)(kr + t));
        float2 sp = up2(s2);
        satt[c * 33 + d] = (sp.x + sp.y) * tscale;
    }
    __syncthreads();

    if (tid < 32) {
        float* rr = satt + tid * 33;
        float mx = rr[0];
        #pragma unroll
        for (int d = 1; d < 32; d++) mx = fmaxf(mx, rr[d]);
        float s = 0.f;
        #pragma unroll
        for (int d = 0; d < 32; d++) { float ev = __expf(rr[d] - mx); rr[d] = ev; s += ev; }
        float inv = 1.f / s;
        #pragma unroll
        for (int d = 0; d < 32; d++) rr[d] *= inv;
    }
    __syncthreads();

    #pragma unroll
    for (int i = 0; i < 16; i++) {
        int e = tid + i * 128;
        int c = e >> 6, t = e & 63;
        const float* ar = satt + c * 33;
        float ov = 0.f;
        #pragma unroll
        for (int d = 0; d < 32; d++) ov += ar[d] * sv[d * 66 + t];
        const float* vr = sv + c * 66;
        const float* mr = sml + t * 66;
        u64 g2 = 0ull;
        #pragma unroll
        for (int x = 0; x < 64; x += 2)
            fma2(g2, *(const u64*)(vr + x), *(const u64*)(mr + x));
        float2 gp = up2(g2);
        float gv = sb[t] + gp.x + gp.y;
        float gl = 0.5f * gv * (1.f + erff(gv * 0.70710678118654752f));
        float res = ov * gl;
        g_t[(((size_t)(b * CDIM + head * CHD + c)) * HDIM + (h1*8 + (t >> 3))) * WDIM
            + w1 * 8 + (t & 7)] = res;
    }
}

// ---------------------------------------------------------------------------
extern "C" void kernel_launch(void* const* d_in, const int* in_sizes, int n_in,
                              void* d_out, int out_size)
{
    const float* x      = (const float*)d_in[0];
    const float* w_qkv  = (const float*)d_in[1];
    const float* w_dw   = (const float*)d_in[2];
    const float* temp   = (const float*)d_in[3];
    const float* mlp_w  = (const float*)d_in[4];
    const float* mlp_b  = (const float*)d_in[5];
    const float* proj_w = (const float*)d_in[6];
    const float* proj_b = (const float*)d_in[7];
    float* out = (float*)d_out;
    (void)in_sizes; (void)n_in; (void)out_size;

    float *p_qkv, *p_t;
    cudaGetSymbolAddress((void**)&p_qkv, g_qkv);
    cudaGetSymbolAddress((void**)&p_t,   g_t);

    cudaFuncSetAttribute(k_gemm_mma, cudaFuncAttributeMaxDynamicSharedMemorySize,
                         SMEM_BYTES);

    // K1: qkv = W_qkv @ x  (M=576, N=131072, K=192), mma.sync split-bf16
    k_gemm_mma<<<dim3(BATCH*HWSZ/NT/PXITER, C3/64), 128, SMEM_BYTES>>>(
        w_qkv, x, p_qkv, nullptr, 0, C3);

    // K2: depthwise 3x3
    k_dw<<<dim3(HDIM/2, C3, BATCH), 128>>>(w_dw);

    // K3: windowed channel attention + gate
    k_attn<<<dim3(NWIN, HEADS), 128>>>(temp, mlp_w, mlp_b);

    // K4: projection (M=192, K=192) + bias -> d_out, mma.sync split-bf16
    k_gemm_mma<<<dim3(BATCH*HWSZ/NT/PXITER, CDIM/64), 128, SMEM_BYTES>>>(
        proj_w, p_t, out, proj_b, 1, CDIM);
}

// round 8
// speedup vs baseline: 1.3173x; 1.3173x over previous
#include <cuda_runtime.h>
#include <cuda_bf16.h>
#include <math.h>
#include <stdint.h>

// Problem constants
#define BATCH 2
#define CDIM  192
#define C3    576
#define HDIM  256
#define WDIM  256
#define HWSZ  (HDIM*WDIM)       // 65536
#define HEADS 6
#define CHD   32
#define NWIN  2048
#define KD    192

#define NT     64               // px per tile
#define PXITER 8                // tiles per CTA
#define KSTEPS 12               // 192/16

// dynamic smem word offsets (uint32 words)
// A: ks*512 + lh*256 + m*4 + tg  (12288 words each not needed; hi 0.., lo 6144..)
// B: frag*776 + ks*64 + k2*8 + nw (8 frags -> 6208 words per copy)
#define W_AHI 0
#define W_ALO 6144
#define W_BHI 12288
#define W_BLO (12288 + 6208)
#define SMEM_WORDS (12288 + 2*6208)
#define SMEM_BYTES (SMEM_WORDS * 4)
#define BFRAG 776

typedef unsigned long long u64;

// ---------------- packed f32x2 helpers (k_attn) ----------------
__device__ __forceinline__ u64 pk1(float x) {
    u64 r; asm("mov.b64 %0,{%1,%1};" : "=l"(r) : "f"(x)); return r;
}
__device__ __forceinline__ void fma2(u64& d, u64 a, u64 b) {
    asm("fma.rn.f32x2 %0,%1,%2,%3;" : "=l"(d) : "l"(a), "l"(b), "l"(d));
}
__device__ __forceinline__ void mul2(u64& d, u64 a, u64 b) {
    asm("mul.rn.f32x2 %0,%1,%2;" : "=l"(d) : "l"(a), "l"(b));
}
__device__ __forceinline__ float2 up2(u64 v) {
    float2 f; asm("mov.b64 {%0,%1},%2;" : "=f"(f.x), "=f"(f.y) : "l"(v)); return f;
}
__device__ __forceinline__ uint32_t prmt(uint32_t a, uint32_t b, uint32_t s) {
    uint32_t d; asm("prmt.b32 %0,%1,%2,%3;" : "=r"(d) : "r"(a), "r"(b), "r"(s));
    return d;
}

// ---------------- bf16 split helpers ----------------
__device__ __forceinline__ void split1(float x, uint32_t& h, uint32_t& l) {
    __nv_bfloat16 hb = __float2bfloat16(x);
    float r = x - __bfloat162float(hb);
    __nv_bfloat16 lb = __float2bfloat16(r);
    h = (uint32_t)__bfloat16_as_ushort(hb);
    l = (uint32_t)__bfloat16_as_ushort(lb);
}
__device__ __forceinline__ void split2(float a, float b, uint32_t& hw, uint32_t& lw) {
    uint32_t ha, la, hb2, lb2;
    split1(a, ha, la); split1(b, hb2, lb2);
    hw = ha | (hb2 << 16);
    lw = la | (lb2 << 16);
}

// mma.sync m16n8k16 bf16 fp32-acc (portable PTX, sm_80+)
__device__ __forceinline__ void mma16816(float* c, const uint32_t* a, const uint32_t* b) {
    asm volatile(
        "mma.sync.aligned.m16n8k16.row.col.f32.bf16.bf16.f32 "
        "{%0,%1,%2,%3},{%4,%5,%6,%7},{%8,%9},{%0,%1,%2,%3};"
        : "+f"(c[0]), "+f"(c[1]), "+f"(c[2]), "+f"(c[3])
        : "r"(a[0]), "r"(a[1]), "r"(a[2]), "r"(a[3]), "r"(b[0]), "r"(b[1]));
}

// Scratch (device globals; no allocation allowed)
__device__ float    g_qkv[(size_t)BATCH*C3*HWSZ];     // K1 output (fp32, feeds dw)
__device__ float    g_dw [(size_t)BATCH*C3*HWSZ];     // dw output (fp32, feeds attn)
__device__ unsigned short g_xhi[(size_t)BATCH*KD*HWSZ];   // split of x (K1 B input)
__device__ unsigned short g_xlo[(size_t)BATCH*KD*HWSZ];
__device__ unsigned short g_thi[(size_t)BATCH*CDIM*HWSZ]; // split attn out (K4 B input)
__device__ unsigned short g_tlo[(size_t)BATCH*CDIM*HWSZ];

// ---------------------------------------------------------------------------
// K0: split fp32 -> bf16 hi/lo global arrays (bandwidth-bound, ~25us)
// ---------------------------------------------------------------------------
__global__ __launch_bounds__(256) void k_split(
    const float* __restrict__ x,
    unsigned short* __restrict__ hi, unsigned short* __restrict__ lo)
{
    size_t i = ((size_t)blockIdx.x * 256 + threadIdx.x) * 4;
    float4 v = *(const float4*)(x + i);
    uint32_t h0, l0, h1, l1;
    split2(v.x, v.y, h0, l0);
    split2(v.z, v.w, h1, l1);
    *(uint2*)(hi + i) = make_uint2(h0, h1);
    *(uint2*)(lo + i) = make_uint2(l0, l1);
}

// ---------------------------------------------------------------------------
// K1/K4: split-bf16 tensor-core GEMM via mma.sync.
// Y[b,m,hw] = sum_k W[m,k] * X[b,k,hw] (+ bias[m]); X pre-split bf16 hi/lo.
// CTA: 256 threads / 8 warps (2M x 4N), tile 64M x 64N, K=192 resident.
// 3 passes: Whi*Xhi + Whi*Xlo + Wlo*Xhi.
// ---------------------------------------------------------------------------
__global__ __launch_bounds__(256) void k_gemm_mma(
    const float* __restrict__ W,
    const unsigned short* __restrict__ Xhi,
    const unsigned short* __restrict__ Xlo,
    float* __restrict__ Y, const float* __restrict__ bias,
    int hasBias, int Mtot)
{
    extern __shared__ uint32_t sm[];
    int tid = threadIdx.x;
    int lane = tid & 31, wid = tid >> 5;
    int g  = lane >> 2, tg = lane & 3;
    int warp_m = wid >> 2, warp_n = wid & 3;
    int m0 = blockIdx.y * 64;

    // ---- stage A (weights) once: 64 rows x 192 k, split hi/lo ----
    for (int u = tid; u < 64 * 48; u += 256) {
        int r = u / 48, q = u % 48;
        int k = q * 4;
        float4 v = *(const float4*)(W + (size_t)(m0 + r) * KD + k);
        uint32_t h0, l0, h1, l1;
        split2(v.x, v.y, h0, l0);
        split2(v.z, v.w, h1, l1);
        int ks = k >> 4, lh = (k >> 3) & 1, tgw = (k >> 1) & 3;
        int idx = ks * 512 + lh * 256 + r * 4 + tgw;
        sm[W_AHI + idx] = h0; sm[W_AHI + idx + 1] = h1;
        sm[W_ALO + idx] = l0; sm[W_ALO + idx + 1] = l1;
    }

    float bv[2][2] = {{0.f,0.f},{0.f,0.f}};
    if (hasBias) {
        #pragma unroll
        for (int mf = 0; mf < 2; mf++) {
            int row = m0 + warp_m * 32 + mf * 16 + g;
            bv[mf][0] = bias[row];
            bv[mf][1] = bias[row + 8];
        }
    }

    for (int it = 0; it < PXITER; ++it) {
        int gp = (blockIdx.x * PXITER + it) * NT;
        int b = gp / HWSZ, hw0 = gp % HWSZ;
        size_t xbase = (size_t)b * KD * HWSZ + hw0;
        __syncthreads();   // previous iter smem reads done (covers A on it=0)

        // ---- stage B from pre-split bf16: LDG.32 + PRMT + STS.64 ----
        for (int u = tid; u < 3072; u += 256) {
            int kp = u >> 5, pp = u & 31;          // k-pair, px-pair
            int k = kp * 2, px = pp * 2;
            const unsigned short* ph = Xhi + xbase + (size_t)k * HWSZ + px;
            const unsigned short* pl = Xlo + xbase + (size_t)k * HWSZ + px;
            uint32_t h0 = *(const uint32_t*)ph;
            uint32_t h1 = *(const uint32_t*)(ph + HWSZ);
            uint32_t l0 = *(const uint32_t*)pl;
            uint32_t l1 = *(const uint32_t*)(pl + HWSZ);
            int ks = kp >> 3, k2w = kp & 7;
            int idx = (px >> 3) * BFRAG + ks * 64 + k2w * 8 + (px & 7);
            *(uint2*)&sm[W_BHI + idx] = make_uint2(prmt(h0,h1,0x5410), prmt(h0,h1,0x7632));
            *(uint2*)&sm[W_BLO + idx] = make_uint2(prmt(l0,l1,0x5410), prmt(l0,l1,0x7632));
        }
        __syncthreads();

        // ---- compute: 3 passes x 12 ksteps x (2 mf x 2 nf) mma per warp ----
        float c[2][2][4];
        #pragma unroll
        for (int mf = 0; mf < 2; mf++)
            #pragma unroll
            for (int nf = 0; nf < 2; nf++)
                #pragma unroll
                for (int i = 0; i < 4; i++) c[mf][nf][i] = 0.f;

        #pragma unroll
        for (int pass = 0; pass < 3; pass++) {
            const uint32_t* A = sm + (pass == 2 ? W_ALO : W_AHI);
            const uint32_t* B = sm + (pass == 1 ? W_BLO : W_BHI);
            #pragma unroll 4
            for (int ks = 0; ks < KSTEPS; ks++) {
                uint32_t af[2][4];
                #pragma unroll
                for (int mf = 0; mf < 2; mf++) {
                    int mb = warp_m * 32 + mf * 16;
                    const uint32_t* Ak = A + ks * 512;
                    af[mf][0] = Ak[(mb + g) * 4 + tg];
                    af[mf][1] = Ak[(mb + 8 + g) * 4 + tg];
                    af[mf][2] = Ak[256 + (mb + g) * 4 + tg];
                    af[mf][3] = Ak[256 + (mb + 8 + g) * 4 + tg];
                }
                uint32_t bfr[2][2];
                #pragma unroll
                for (int nf = 0; nf < 2; nf++) {
                    const uint32_t* Bk = B + (warp_n * 2 + nf) * BFRAG + ks * 64;
                    bfr[nf][0] = Bk[tg * 8 + g];
                    bfr[nf][1] = Bk[(tg + 4) * 8 + g];
                }
                #pragma unroll
                for (int mf = 0; mf < 2; mf++)
                    #pragma unroll
                    for (int nf = 0; nf < 2; nf++)
                        mma16816(c[mf][nf], af[mf], bfr[nf]);
            }
        }

        // ---- epilogue: direct STG (4-lane group = one 32B sector) ----
        #pragma unroll
        for (int mf = 0; mf < 2; mf++) {
            int row0 = m0 + warp_m * 32 + mf * 16 + g;
            #pragma unroll
            for (int nf = 0; nf < 2; nf++) {
                int px = hw0 + (warp_n * 2 + nf) * 8 + tg * 2;
                float* d0 = Y + ((size_t)b * Mtot + row0) * HWSZ + px;
                float* d1 = Y + ((size_t)b * Mtot + row0 + 8) * HWSZ + px;
                *(float2*)d0 = make_float2(c[mf][nf][0] + bv[mf][0], c[mf][nf][1] + bv[mf][0]);
                *(float2*)d1 = make_float2(c[mf][nf][2] + bv[mf][1], c[mf][nf][3] + bv[mf][1]);
            }
        }
    }
}

// ---------------------------------------------------------------------------
// K2: depthwise 3x3, zero pad 1. float4 per thread (4 px). 128 thr = 2 rows.
// ---------------------------------------------------------------------------
__global__ __launch_bounds__(128) void k_dw(const float* __restrict__ w_dw)
{
    int tid = threadIdx.x;
    int ty = tid >> 6, tx = tid & 63;
    int y  = blockIdx.x * 2 + ty;
    int ch = blockIdx.y;
    int b  = blockIdx.z;
    int x0 = tx << 2;

    const float* wk = w_dw + ch * 9;
    size_t base = ((size_t)b * C3 + ch) * HWSZ;
    const float* src = g_qkv + base;

    float4 o = make_float4(0.f, 0.f, 0.f, 0.f);

    #pragma unroll
    for (int dy = -1; dy <= 1; dy++) {
        int yy = y + dy;
        if (yy < 0 || yy >= HDIM) continue;
        const float* row = src + (size_t)yy * WDIM + x0;
        float4 m = *(const float4*)row;
        float lft = (x0 > 0)   ? row[-1] : 0.f;
        float rgt = (x0 < 252) ? row[4]  : 0.f;
        float wl = wk[(dy+1)*3], wc = wk[(dy+1)*3+1], wr = wk[(dy+1)*3+2];
        o.x += wl*lft + wc*m.x + wr*m.y;
        o.y += wl*m.x + wc*m.y + wr*m.z;
        o.z += wl*m.y + wc*m.z + wr*m.w;
        o.w += wl*m.z + wc*m.w + wr*rgt;
    }
    *(float4*)(g_dw + base + (size_t)y * WDIM + x0) = o;
}

// ---------------------------------------------------------------------------
// K3: fused windowed channel attention per (window, head). f32x2 dots.
// Writes output pre-split as bf16 hi/lo (consumed by K4 GEMM).
// ---------------------------------------------------------------------------
__global__ __launch_bounds__(128) void k_attn(
    const float* __restrict__ temp,
    const float* __restrict__ mlp_w,
    const float* __restrict__ mlp_b)
{
    __shared__ float sq[32 * 66];
    __shared__ float sk[32 * 66];
    __shared__ float sv[32 * 66];
    __shared__ float satt[32 * 33];
    __shared__ float sml[64 * 66];
    __shared__ float sb[64];

    int tid  = threadIdx.x;
    int wi   = blockIdx.x;
    int head = blockIdx.y;
    int b  = wi >> 10;
    int r  = wi & 1023;
    int h1 = r >> 5, w1 = r & 31;

    float tscale = temp[head];

    for (int i = tid; i < 1536; i += 128) {
        int z = i / 512;
        int rr = i - z * 512;
        int c  = rr >> 4;
        int q8 = rr & 15;
        int ty = q8 >> 1, half = q8 & 1;
        const float* gp = g_dw +
            (((size_t)(b * C3 + z * CDIM + head * CHD + c)) * HDIM + (h1*8 + ty)) * WDIM
            + w1 * 8 + half * 4;
        float4 v = *(const float4*)gp;
        float* s = (z == 0 ? sq : (z == 1 ? sk : sv)) + c * 66 + ty * 8 + half * 4;
        s[0] = v.x; s[1] = v.y; s[2] = v.z; s[3] = v.w;
    }
    for (int i = tid; i < 4096; i += 128)
        sml[(i >> 6) * 66 + (i & 63)] = mlp_w[i];
    if (tid < 64) sb[tid] = mlp_b[tid];
    __syncthreads();

    if (tid < 64) {
        float* row = (tid < 32) ? (sq + tid * 66) : (sk + (tid - 32) * 66);
        u64 s2 = 0ull;
        #pragma unroll
        for (int t = 0; t < 64; t += 2) {
            u64 v = *(const u64*)(row + t);
            fma2(s2, v, v);
        }
        float2 sp = up2(s2);
        float n = fmaxf(sqrtf(sp.x + sp.y), 1e-12f);
        u64 inv = pk1(1.f / n);
        #pragma unroll
        for (int t = 0; t < 64; t += 2) {
            u64 v = *(const u64*)(row + t);
            mul2(v, v, inv);
            *(u64*)(row + t) = v;
        }
    }
    __syncthreads();

    #pragma unroll
    for (int i = 0; i < 8; i++) {
        int e = tid + i * 128;
        int c = e >> 5, d = e & 31;
        const float* qr = sq + c * 66;
        const float* kr = sk + d * 66;
        u64 s2 = 0ull;
        #pragma unroll
        for (int t = 0; t < 64; t += 2)
            fma2(s2, *(const u64*)(qr + t), *(const u64*)(kr + t));
        float2 sp = up2(s2);
        satt[c * 33 + d] = (sp.x + sp.y) * tscale;
    }
    __syncthreads();

    if (tid < 32) {
        float* rr = satt + tid * 33;
        float mx = rr[0];
        #pragma unroll
        for (int d = 1; d < 32; d++) mx = fmaxf(mx, rr[d]);
        float s = 0.f;
        #pragma unroll
        for (int d = 0; d < 32; d++) { float ev = __expf(rr[d] - mx); rr[d] = ev; s += ev; }
        float inv = 1.f / s;
        #pragma unroll
        for (int d = 0; d < 32; d++) rr[d] *= inv;
    }
    __syncthreads();

    #pragma unroll
    for (int i = 0; i < 16; i++) {
        int e = tid + i * 128;
        int c = e >> 6, t = e & 63;
        const float* ar = satt + c * 33;
        float ov = 0.f;
        #pragma unroll
        for (int d = 0; d < 32; d++) ov += ar[d] * sv[d * 66 + t];
        const float* vr = sv + c * 66;
        const float* mr = sml + t * 66;
        u64 g2 = 0ull;
        #pragma unroll
        for (int x = 0; x < 64; x += 2)
            fma2(g2, *(const u64*)(vr + x), *(const u64*)(mr + x));
        float2 gp = up2(g2);
        float gv = sb[t] + gp.x + gp.y;
        float gl = 0.5f * gv * (1.f + erff(gv * 0.70710678118654752f));
        float res = ov * gl;
        size_t oidx = (((size_t)(b * CDIM + head * CHD + c)) * HDIM + (h1*8 + (t >> 3))) * WDIM
                      + w1 * 8 + (t & 7);
        uint32_t rh, rl;
        split1(res, rh, rl);
        g_thi[oidx] = (unsigned short)rh;
        g_tlo[oidx] = (unsigned short)rl;
    }
}

// ---------------------------------------------------------------------------
extern "C" void kernel_launch(void* const* d_in, const int* in_sizes, int n_in,
                              void* d_out, int out_size)
{
    const float* x      = (const float*)d_in[0];
    const float* w_qkv  = (const float*)d_in[1];
    const float* w_dw   = (const float*)d_in[2];
    const float* temp   = (const float*)d_in[3];
    const float* mlp_w  = (const float*)d_in[4];
    const float* mlp_b  = (const float*)d_in[5];
    const float* proj_w = (const float*)d_in[6];
    const float* proj_b = (const float*)d_in[7];
    float* out = (float*)d_out;
    (void)in_sizes; (void)n_in; (void)out_size;

    float *p_qkv;
    unsigned short *p_xhi, *p_xlo, *p_thi, *p_tlo;
    cudaGetSymbolAddress((void**)&p_qkv, g_qkv);
    cudaGetSymbolAddress((void**)&p_xhi, g_xhi);
    cudaGetSymbolAddress((void**)&p_xlo, g_xlo);
    cudaGetSymbolAddress((void**)&p_thi, g_thi);
    cudaGetSymbolAddress((void**)&p_tlo, g_tlo);

    cudaFuncSetAttribute(k_gemm_mma, cudaFuncAttributeMaxDynamicSharedMemorySize,
                         SMEM_BYTES);

    // K0: split x into bf16 hi/lo
    k_split<<<(BATCH*KD*HWSZ)/(256*4), 256>>>(x, p_xhi, p_xlo);

    // K1: qkv = W_qkv @ x  (M=576, N=131072, K=192)
    k_gemm_mma<<<dim3(BATCH*HWSZ/NT/PXITER, C3/64), 256, SMEM_BYTES>>>(
        w_qkv, p_xhi, p_xlo, p_qkv, nullptr, 0, C3);

    // K2: depthwise 3x3
    k_dw<<<dim3(HDIM/2, C3, BATCH), 128>>>(w_dw);

    // K3: windowed channel attention + gate (writes split bf16)
    k_attn<<<dim3(NWIN, HEADS), 128>>>(temp, mlp_w, mlp_b);

    // K4: projection (M=192, K=192) + bias -> d_out
    k_gemm_mma<<<dim3(BATCH*HWSZ/NT/PXITER, CDIM/64), 256, SMEM_BYTES>>>(
        proj_w, p_thi, p_tlo, out, proj_b, 1, CDIM);
}

// round 9
// speedup vs baseline: 1.3752x; 1.0439x over previous
#include <cuda_runtime.h>
#include <cuda_bf16.h>
#include <math.h>
#include <stdint.h>

// Problem constants
#define BATCH 2
#define CDIM  192
#define C3    576
#define HDIM  256
#define WDIM  256
#define HWSZ  (HDIM*WDIM)       // 65536
#define HEADS 6
#define CHD   32
#define NWIN  2048
#define KD    192

#define NT     64               // px per tile
#define PXITER 8                // tiles per CTA
#define KSTEPS 12               // 192/16

// dynamic smem word offsets (uint32 words)
#define W_AHI 0
#define W_ALO 6144
#define W_BHI 12288
#define W_BLO (12288 + 6208)
#define SMEM_WORDS (12288 + 2*6208)
#define SMEM_BYTES (SMEM_WORDS * 4)
#define BFRAG 776

typedef unsigned long long u64;

// ---------------- packed f32x2 helpers ----------------
__device__ __forceinline__ u64 pk1(float x) {
    u64 r; asm("mov.b64 %0,{%1,%1};" : "=l"(r) : "f"(x)); return r;
}
__device__ __forceinline__ void fma2(u64& d, u64 a, u64 b) {
    asm("fma.rn.f32x2 %0,%1,%2,%3;" : "=l"(d) : "l"(a), "l"(b), "l"(d));
}
__device__ __forceinline__ void mul2(u64& d, u64 a, u64 b) {
    asm("mul.rn.f32x2 %0,%1,%2;" : "=l"(d) : "l"(a), "l"(b));
}
__device__ __forceinline__ float2 up2(u64 v) {
    float2 f; asm("mov.b64 {%0,%1},%2;" : "=f"(f.x), "=f"(f.y) : "l"(v)); return f;
}
__device__ __forceinline__ uint32_t prmt(uint32_t a, uint32_t b, uint32_t s) {
    uint32_t d; asm("prmt.b32 %0,%1,%2,%3;" : "=r"(d) : "r"(a), "r"(b), "r"(s));
    return d;
}

// ---------------- bf16 split helpers ----------------
__device__ __forceinline__ void split1(float x, uint32_t& h, uint32_t& l) {
    __nv_bfloat16 hb = __float2bfloat16(x);
    float r = x - __bfloat162float(hb);
    __nv_bfloat16 lb = __float2bfloat16(r);
    h = (uint32_t)__bfloat16_as_ushort(hb);
    l = (uint32_t)__bfloat16_as_ushort(lb);
}
__device__ __forceinline__ void split2(float a, float b, uint32_t& hw, uint32_t& lw) {
    uint32_t ha, la, hb2, lb2;
    split1(a, ha, la); split1(b, hb2, lb2);
    hw = ha | (hb2 << 16);
    lw = la | (lb2 << 16);
}

// mma.sync m16n8k16 bf16 fp32-acc (portable PTX, sm_80+)
__device__ __forceinline__ void mma16816(float* c, const uint32_t* a, const uint32_t* b) {
    asm volatile(
        "mma.sync.aligned.m16n8k16.row.col.f32.bf16.bf16.f32 "
        "{%0,%1,%2,%3},{%4,%5,%6,%7},{%8,%9},{%0,%1,%2,%3};"
        : "+f"(c[0]), "+f"(c[1]), "+f"(c[2]), "+f"(c[3])
        : "r"(a[0]), "r"(a[1]), "r"(a[2]), "r"(a[3]), "r"(b[0]), "r"(b[1]));
}

// Scratch (device globals; no allocation allowed)
__device__ float    g_qkv[(size_t)BATCH*C3*HWSZ];
__device__ float    g_dw [(size_t)BATCH*C3*HWSZ];
__device__ unsigned short g_xhi[(size_t)BATCH*KD*HWSZ];
__device__ unsigned short g_xlo[(size_t)BATCH*KD*HWSZ];
__device__ unsigned short g_thi[(size_t)BATCH*CDIM*HWSZ];
__device__ unsigned short g_tlo[(size_t)BATCH*CDIM*HWSZ];

// ---------------------------------------------------------------------------
// K0: split fp32 -> bf16 hi/lo global arrays
// ---------------------------------------------------------------------------
__global__ __launch_bounds__(256) void k_split(
    const float* __restrict__ x,
    unsigned short* __restrict__ hi, unsigned short* __restrict__ lo)
{
    size_t i = ((size_t)blockIdx.x * 256 + threadIdx.x) * 4;
    float4 v = *(const float4*)(x + i);
    uint32_t h0, l0, h1, l1;
    split2(v.x, v.y, h0, l0);
    split2(v.z, v.w, h1, l1);
    *(uint2*)(hi + i) = make_uint2(h0, h1);
    *(uint2*)(lo + i) = make_uint2(l0, l1);
}

// ---------------------------------------------------------------------------
// K1/K4: split-bf16 tensor-core GEMM via mma.sync (unchanged from R8).
// ---------------------------------------------------------------------------
__global__ __launch_bounds__(256) void k_gemm_mma(
    const float* __restrict__ W,
    const unsigned short* __restrict__ Xhi,
    const unsigned short* __restrict__ Xlo,
    float* __restrict__ Y, const float* __restrict__ bias,
    int hasBias, int Mtot)
{
    extern __shared__ uint32_t sm[];
    int tid = threadIdx.x;
    int lane = tid & 31, wid = tid >> 5;
    int g  = lane >> 2, tg = lane & 3;
    int warp_m = wid >> 2, warp_n = wid & 3;
    int m0 = blockIdx.y * 64;

    for (int u = tid; u < 64 * 48; u += 256) {
        int r = u / 48, q = u % 48;
        int k = q * 4;
        float4 v = *(const float4*)(W + (size_t)(m0 + r) * KD + k);
        uint32_t h0, l0, h1, l1;
        split2(v.x, v.y, h0, l0);
        split2(v.z, v.w, h1, l1);
        int ks = k >> 4, lh = (k >> 3) & 1, tgw = (k >> 1) & 3;
        int idx = ks * 512 + lh * 256 + r * 4 + tgw;
        sm[W_AHI + idx] = h0; sm[W_AHI + idx + 1] = h1;
        sm[W_ALO + idx] = l0; sm[W_ALO + idx + 1] = l1;
    }

    float bv[2][2] = {{0.f,0.f},{0.f,0.f}};
    if (hasBias) {
        #pragma unroll
        for (int mf = 0; mf < 2; mf++) {
            int row = m0 + warp_m * 32 + mf * 16 + g;
            bv[mf][0] = bias[row];
            bv[mf][1] = bias[row + 8];
        }
    }

    for (int it = 0; it < PXITER; ++it) {
        int gp = (blockIdx.x * PXITER + it) * NT;
        int b = gp / HWSZ, hw0 = gp % HWSZ;
        size_t xbase = (size_t)b * KD * HWSZ + hw0;
        __syncthreads();

        for (int u = tid; u < 3072; u += 256) {
            int kp = u >> 5, pp = u & 31;
            int k = kp * 2, px = pp * 2;
            const unsigned short* ph = Xhi + xbase + (size_t)k * HWSZ + px;
            const unsigned short* pl = Xlo + xbase + (size_t)k * HWSZ + px;
            uint32_t h0 = *(const uint32_t*)ph;
            uint32_t h1 = *(const uint32_t*)(ph + HWSZ);
            uint32_t l0 = *(const uint32_t*)pl;
            uint32_t l1 = *(const uint32_t*)(pl + HWSZ);
            int ks = kp >> 3, k2w = kp & 7;
            int idx = (px >> 3) * BFRAG + ks * 64 + k2w * 8 + (px & 7);
            *(uint2*)&sm[W_BHI + idx] = make_uint2(prmt(h0,h1,0x5410), prmt(h0,h1,0x7632));
            *(uint2*)&sm[W_BLO + idx] = make_uint2(prmt(l0,l1,0x5410), prmt(l0,l1,0x7632));
        }
        __syncthreads();

        float c[2][2][4];
        #pragma unroll
        for (int mf = 0; mf < 2; mf++)
            #pragma unroll
            for (int nf = 0; nf < 2; nf++)
                #pragma unroll
                for (int i = 0; i < 4; i++) c[mf][nf][i] = 0.f;

        #pragma unroll
        for (int pass = 0; pass < 3; pass++) {
            const uint32_t* A = sm + (pass == 2 ? W_ALO : W_AHI);
            const uint32_t* B = sm + (pass == 1 ? W_BLO : W_BHI);
            #pragma unroll 4
            for (int ks = 0; ks < KSTEPS; ks++) {
                uint32_t af[2][4];
                #pragma unroll
                for (int mf = 0; mf < 2; mf++) {
                    int mb = warp_m * 32 + mf * 16;
                    const uint32_t* Ak = A + ks * 512;
                    af[mf][0] = Ak[(mb + g) * 4 + tg];
                    af[mf][1] = Ak[(mb + 8 + g) * 4 + tg];
                    af[mf][2] = Ak[256 + (mb + g) * 4 + tg];
                    af[mf][3] = Ak[256 + (mb + 8 + g) * 4 + tg];
                }
                uint32_t bfr[2][2];
                #pragma unroll
                for (int nf = 0; nf < 2; nf++) {
                    const uint32_t* Bk = B + (warp_n * 2 + nf) * BFRAG + ks * 64;
                    bfr[nf][0] = Bk[tg * 8 + g];
                    bfr[nf][1] = Bk[(tg + 4) * 8 + g];
                }
                #pragma unroll
                for (int mf = 0; mf < 2; mf++)
                    #pragma unroll
                    for (int nf = 0; nf < 2; nf++)
                        mma16816(c[mf][nf], af[mf], bfr[nf]);
            }
        }

        #pragma unroll
        for (int mf = 0; mf < 2; mf++) {
            int row0 = m0 + warp_m * 32 + mf * 16 + g;
            #pragma unroll
            for (int nf = 0; nf < 2; nf++) {
                int px = hw0 + (warp_n * 2 + nf) * 8 + tg * 2;
                float* d0 = Y + ((size_t)b * Mtot + row0) * HWSZ + px;
                float* d1 = Y + ((size_t)b * Mtot + row0 + 8) * HWSZ + px;
                *(float2*)d0 = make_float2(c[mf][nf][0] + bv[mf][0], c[mf][nf][1] + bv[mf][0]);
                *(float2*)d1 = make_float2(c[mf][nf][2] + bv[mf][1], c[mf][nf][3] + bv[mf][1]);
            }
        }
    }
}

// ---------------------------------------------------------------------------
// K2: depthwise 3x3 (unchanged)
// ---------------------------------------------------------------------------
__global__ __launch_bounds__(128) void k_dw(const float* __restrict__ w_dw)
{
    int tid = threadIdx.x;
    int ty = tid >> 6, tx = tid & 63;
    int y  = blockIdx.x * 2 + ty;
    int ch = blockIdx.y;
    int b  = blockIdx.z;
    int x0 = tx << 2;

    const float* wk = w_dw + ch * 9;
    size_t base = ((size_t)b * C3 + ch) * HWSZ;
    const float* src = g_qkv + base;

    float4 o = make_float4(0.f, 0.f, 0.f, 0.f);

    #pragma unroll
    for (int dy = -1; dy <= 1; dy++) {
        int yy = y + dy;
        if (yy < 0 || yy >= HDIM) continue;
        const float* row = src + (size_t)yy * WDIM + x0;
        float4 m = *(const float4*)row;
        float lft = (x0 > 0)   ? row[-1] : 0.f;
        float rgt = (x0 < 252) ? row[4]  : 0.f;
        float wl = wk[(dy+1)*3], wc = wk[(dy+1)*3+1], wr = wk[(dy+1)*3+2];
        o.x += wl*lft + wc*m.x + wr*m.y;
        o.y += wl*m.x + wc*m.y + wr*m.z;
        o.z += wl*m.y + wc*m.z + wr*m.w;
        o.w += wl*m.z + wc*m.w + wr*rgt;
    }
    *(float4*)(g_dw + base + (size_t)y * WDIM + x0) = o;
}

// ---------------------------------------------------------------------------
// K3: windowed channel attention, register-tiled.
//   qk: 2c x 4d per thread.  out+gate: 4c x 4t per thread.
//   mlp stored transposed (sml[x][t], stride 66) so gate accumulates t-pairs.
//   Output written pre-split bf16 hi/lo, paired u32 stores.
// ---------------------------------------------------------------------------
__global__ __launch_bounds__(128) void k_attn(
    const float* __restrict__ temp,
    const float* __restrict__ mlp_w,
    const float* __restrict__ mlp_b)
{
    __shared__ float sq[32 * 66];
    __shared__ float sk[32 * 66];
    __shared__ float sv[32 * 66];
    __shared__ float satt[32 * 33];
    __shared__ float sml[64 * 66];     // TRANSPOSED: sml[x*66 + t] = mlp_w[t][x]
    __shared__ float sb[64];

    int tid  = threadIdx.x;
    int wi   = blockIdx.x;
    int head = blockIdx.y;
    int b  = wi >> 10;
    int r  = wi & 1023;
    int h1 = r >> 5, w1 = r & 31;

    float tscale = temp[head];

    // --- load q/k/v (32ch x 64tok), float4 global reads ---
    for (int i = tid; i < 1536; i += 128) {
        int z = i / 512;
        int rr = i - z * 512;
        int c  = rr >> 4;
        int q8 = rr & 15;
        int ty = q8 >> 1, half = q8 & 1;
        const float* gp = g_dw +
            (((size_t)(b * C3 + z * CDIM + head * CHD + c)) * HDIM + (h1*8 + ty)) * WDIM
            + w1 * 8 + half * 4;
        float4 v = *(const float4*)gp;
        float* s = (z == 0 ? sq : (z == 1 ? sk : sv)) + c * 66 + ty * 8 + half * 4;
        s[0] = v.x; s[1] = v.y; s[2] = v.z; s[3] = v.w;
    }
    // mlp transposed: sml[x][t] = mlp_w[t*64+x]
    for (int i = tid; i < 4096; i += 128)
        sml[(i & 63) * 66 + (i >> 6)] = mlp_w[i];
    if (tid < 64) sb[tid] = mlp_b[tid];
    __syncthreads();

    // --- l2 normalize q and k rows ---
    if (tid < 64) {
        float* row = (tid < 32) ? (sq + tid * 66) : (sk + (tid - 32) * 66);
        u64 s2 = 0ull;
        #pragma unroll
        for (int t = 0; t < 64; t += 2) {
            u64 v = *(const u64*)(row + t);
            fma2(s2, v, v);
        }
        float2 sp = up2(s2);
        float n = fmaxf(sqrtf(sp.x + sp.y), 1e-12f);
        u64 inv = pk1(1.f / n);
        #pragma unroll
        for (int t = 0; t < 64; t += 2) {
            u64 v = *(const u64*)(row + t);
            mul2(v, v, inv);
            *(u64*)(row + t) = v;
        }
    }
    __syncthreads();

    // --- qk: thread tile 2c x 4d ---
    {
        int cb = tid >> 3, db = tid & 7;     // c0 = cb*2, d0 = db*4
        int c0 = cb * 2, d0 = db * 4;
        u64 acc[2][4];
        #pragma unroll
        for (int i = 0; i < 2; i++)
            #pragma unroll
            for (int j = 0; j < 4; j++) acc[i][j] = 0ull;
        const float* q0 = sq + c0 * 66;
        const float* k0 = sk + d0 * 66;
        #pragma unroll
        for (int t = 0; t < 64; t += 2) {
            u64 qa = *(const u64*)(q0 + t);
            u64 qb = *(const u64*)(q0 + 66 + t);
            u64 k_0 = *(const u64*)(k0 + t);
            u64 k_1 = *(const u64*)(k0 + 66 + t);
            u64 k_2 = *(const u64*)(k0 + 132 + t);
            u64 k_3 = *(const u64*)(k0 + 198 + t);
            fma2(acc[0][0], qa, k_0); fma2(acc[0][1], qa, k_1);
            fma2(acc[0][2], qa, k_2); fma2(acc[0][3], qa, k_3);
            fma2(acc[1][0], qb, k_0); fma2(acc[1][1], qb, k_1);
            fma2(acc[1][2], qb, k_2); fma2(acc[1][3], qb, k_3);
        }
        #pragma unroll
        for (int i = 0; i < 2; i++)
            #pragma unroll
            for (int j = 0; j < 4; j++) {
                float2 sp = up2(acc[i][j]);
                satt[(c0 + i) * 33 + d0 + j] = (sp.x + sp.y) * tscale;
            }
    }
    __syncthreads();

    // --- softmax over d ---
    if (tid < 32) {
        float* rr = satt + tid * 33;
        float mx = rr[0];
        #pragma unroll
        for (int d = 1; d < 32; d++) mx = fmaxf(mx, rr[d]);
        float s = 0.f;
        #pragma unroll
        for (int d = 0; d < 32; d++) { float ev = __expf(rr[d] - mx); rr[d] = ev; s += ev; }
        float inv = 1.f / s;
        #pragma unroll
        for (int d = 0; d < 32; d++) rr[d] *= inv;
    }
    __syncthreads();

    // --- out + gate: thread tile 4c x 4t ---
    {
        int cb = tid >> 4, tb = tid & 15;    // c0 = cb*4, t0 = tb*4
        int c0 = cb * 4, t0 = tb * 4;

        // out[c][t] = sum_d attn[c][d] * v[d][t]
        u64 oacc[4][2];
        #pragma unroll
        for (int i = 0; i < 4; i++) { oacc[i][0] = 0ull; oacc[i][1] = 0ull; }
        #pragma unroll 8
        for (int d = 0; d < 32; d++) {
            u64 v0 = *(const u64*)(sv + d * 66 + t0);
            u64 v1 = *(const u64*)(sv + d * 66 + t0 + 2);
            #pragma unroll
            for (int i = 0; i < 4; i++) {
                u64 ap = pk1(satt[(c0 + i) * 33 + d]);
                fma2(oacc[i][0], ap, v0);
                fma2(oacc[i][1], ap, v1);
            }
        }

        // gate[c][t] = sum_x v[c][x] * mlp_w[t][x]  (sml transposed)
        u64 gacc[4][2];
        #pragma unroll
        for (int i = 0; i < 4; i++) { gacc[i][0] = 0ull; gacc[i][1] = 0ull; }
        #pragma unroll 8
        for (int x = 0; x < 64; x++) {
            u64 m0 = *(const u64*)(sml + x * 66 + t0);
            u64 m1 = *(const u64*)(sml + x * 66 + t0 + 2);
            #pragma unroll
            for (int i = 0; i < 4; i++) {
                u64 vp = pk1(sv[(c0 + i) * 66 + x]);
                fma2(gacc[i][0], vp, m0);
                fma2(gacc[i][1], vp, m1);
            }
        }

        float b0 = sb[t0], b1 = sb[t0+1], b2 = sb[t0+2], b3 = sb[t0+3];
        #pragma unroll
        for (int i = 0; i < 4; i++) {
            int c = c0 + i;
            float2 o0 = up2(oacc[i][0]), o1 = up2(oacc[i][1]);
            float2 g0 = up2(gacc[i][0]), g1 = up2(gacc[i][1]);
            float gv0 = g0.x + b0, gv1 = g0.y + b1, gv2 = g1.x + b2, gv3 = g1.y + b3;
            const float is2 = 0.70710678118654752f;
            float r0 = o0.x * (0.5f * gv0 * (1.f + erff(gv0 * is2)));
            float r1 = o0.y * (0.5f * gv1 * (1.f + erff(gv1 * is2)));
            float r2 = o1.x * (0.5f * gv2 * (1.f + erff(gv2 * is2)));
            float r3 = o1.y * (0.5f * gv3 * (1.f + erff(gv3 * is2)));
            // t0..t0+3 are contiguous in output (t0 % 8 in {0,4})
            size_t base = (((size_t)(b * CDIM + head * CHD + c)) * HDIM
                           + (h1*8 + (t0 >> 3))) * WDIM + w1 * 8 + (t0 & 7);
            uint32_t h0_, l0_, h1_, l1_;
            split2(r0, r1, h0_, l0_);
            split2(r2, r3, h1_, l1_);
            *(uint32_t*)(g_thi + base)     = h0_;
            *(uint32_t*)(g_thi + base + 2) = h1_;
            *(uint32_t*)(g_tlo + base)     = l0_;
            *(uint32_t*)(g_tlo + base + 2) = l1_;
        }
    }
}

// ---------------------------------------------------------------------------
extern "C" void kernel_launch(void* const* d_in, const int* in_sizes, int n_in,
                              void* d_out, int out_size)
{
    const float* x      = (const float*)d_in[0];
    const float* w_qkv  = (const float*)d_in[1];
    const float* w_dw   = (const float*)d_in[2];
    const float* temp   = (const float*)d_in[3];
    const float* mlp_w  = (const float*)d_in[4];
    const float* mlp_b  = (const float*)d_in[5];
    const float* proj_w = (const float*)d_in[6];
    const float* proj_b = (const float*)d_in[7];
    float* out = (float*)d_out;
    (void)in_sizes; (void)n_in; (void)out_size;

    float *p_qkv;
    unsigned short *p_xhi, *p_xlo, *p_thi, *p_tlo;
    cudaGetSymbolAddress((void**)&p_qkv, g_qkv);
    cudaGetSymbolAddress((void**)&p_xhi, g_xhi);
    cudaGetSymbolAddress((void**)&p_xlo, g_xlo);
    cudaGetSymbolAddress((void**)&p_thi, g_thi);
    cudaGetSymbolAddress((void**)&p_tlo, g_tlo);

    cudaFuncSetAttribute(k_gemm_mma, cudaFuncAttributeMaxDynamicSharedMemorySize,
                         SMEM_BYTES);

    // K0: split x into bf16 hi/lo
    k_split<<<(BATCH*KD*HWSZ)/(256*4), 256>>>(x, p_xhi, p_xlo);

    // K1: qkv = W_qkv @ x  (M=576, N=131072, K=192)
    k_gemm_mma<<<dim3(BATCH*HWSZ/NT/PXITER, C3/64), 256, SMEM_BYTES>>>(
        w_qkv, p_xhi, p_xlo, p_qkv, nullptr, 0, C3);

    // K2: depthwise 3x3
    k_dw<<<dim3(HDIM/2, C3, BATCH), 128>>>(w_dw);

    // K3: windowed channel attention + gate (register-tiled, writes split bf16)
    k_attn<<<dim3(NWIN, HEADS), 128>>>(temp, mlp_w, mlp_b);

    // K4: projection (M=192, K=192) + bias -> d_out
    k_gemm_mma<<<dim3(BATCH*HWSZ/NT/PXITER, CDIM/64), 256, SMEM_BYTES>>>(
        proj_w, p_thi, p_tlo, out, proj_b, 1, CDIM);
}

// round 10
// speedup vs baseline: 1.4379x; 1.0456x over previous
#include <cuda_runtime.h>
#include <cuda_bf16.h>
#include <math.h>
#include <stdint.h>

// Problem constants
#define BATCH 2
#define CDIM  192
#define C3    576
#define HDIM  256
#define WDIM  256
#define HWSZ  (HDIM*WDIM)       // 65536
#define HEADS 6
#define CHD   32
#define NWIN  2048
#define KD    192

#define NT     64               // px per tile
#define PXITER 8                // tiles per CTA
#define KSTEPS 12               // 192/16

// dynamic smem word offsets (uint32 words)
#define W_AHI 0
#define W_ALO 6144
#define W_BHI 12288
#define W_BLO (12288 + 6208)
#define SMEM_WORDS (12288 + 2*6208)
#define SMEM_BYTES (SMEM_WORDS * 4)
#define BFRAG 776

typedef unsigned long long u64;

// ---------------- packed f32x2 helpers ----------------
__device__ __forceinline__ u64 pk1(float x) {
    u64 r; asm("mov.b64 %0,{%1,%1};" : "=l"(r) : "f"(x)); return r;
}
__device__ __forceinline__ void fma2(u64& d, u64 a, u64 b) {
    asm("fma.rn.f32x2 %0,%1,%2,%3;" : "=l"(d) : "l"(a), "l"(b), "l"(d));
}
__device__ __forceinline__ void mul2(u64& d, u64 a, u64 b) {
    asm("mul.rn.f32x2 %0,%1,%2;" : "=l"(d) : "l"(a), "l"(b));
}
__device__ __forceinline__ float2 up2(u64 v) {
    float2 f; asm("mov.b64 {%0,%1},%2;" : "=f"(f.x), "=f"(f.y) : "l"(v)); return f;
}
__device__ __forceinline__ uint32_t prmt(uint32_t a, uint32_t b, uint32_t s) {
    uint32_t d; asm("prmt.b32 %0,%1,%2,%3;" : "=r"(d) : "r"(a), "r"(b), "r"(s));
    return d;
}

// ---------------- bf16 split helpers ----------------
__device__ __forceinline__ void split1(float x, uint32_t& h, uint32_t& l) {
    __nv_bfloat16 hb = __float2bfloat16(x);
    float r = x - __bfloat162float(hb);
    __nv_bfloat16 lb = __float2bfloat16(r);
    h = (uint32_t)__bfloat16_as_ushort(hb);
    l = (uint32_t)__bfloat16_as_ushort(lb);
}
__device__ __forceinline__ void split2(float a, float b, uint32_t& hw, uint32_t& lw) {
    uint32_t ha, la, hb2, lb2;
    split1(a, ha, la); split1(b, hb2, lb2);
    hw = ha | (hb2 << 16);
    lw = la | (lb2 << 16);
}

// mma.sync m16n8k16 bf16 fp32-acc
__device__ __forceinline__ void mma16816(float* c, const uint32_t* a, const uint32_t* b) {
    asm volatile(
        "mma.sync.aligned.m16n8k16.row.col.f32.bf16.bf16.f32 "
        "{%0,%1,%2,%3},{%4,%5,%6,%7},{%8,%9},{%0,%1,%2,%3};"
        : "+f"(c[0]), "+f"(c[1]), "+f"(c[2]), "+f"(c[3])
        : "r"(a[0]), "r"(a[1]), "r"(a[2]), "r"(a[3]), "r"(b[0]), "r"(b[1]));
}

// Scratch (device globals; no allocation allowed)
__device__ float    g_qkv[(size_t)BATCH*C3*HWSZ];     // K1 out; later reused as attn-out scratch
__device__ float    g_dw [(size_t)BATCH*C3*HWSZ];
__device__ unsigned short g_xhi[(size_t)BATCH*KD*HWSZ];
__device__ unsigned short g_xlo[(size_t)BATCH*KD*HWSZ];
__device__ unsigned short g_thi[(size_t)BATCH*CDIM*HWSZ];
__device__ unsigned short g_tlo[(size_t)BATCH*CDIM*HWSZ];

// ---------------------------------------------------------------------------
// K0: split fp32 -> bf16 hi/lo
// ---------------------------------------------------------------------------
__global__ __launch_bounds__(256) void k_split(
    const float* __restrict__ x,
    unsigned short* __restrict__ hi, unsigned short* __restrict__ lo)
{
    size_t i = ((size_t)blockIdx.x * 256 + threadIdx.x) * 4;
    float4 v = *(const float4*)(x + i);
    uint32_t h0, l0, h1, l1;
    split2(v.x, v.y, h0, l0);
    split2(v.z, v.w, h1, l1);
    *(uint2*)(hi + i) = make_uint2(h0, h1);
    *(uint2*)(lo + i) = make_uint2(l0, l1);
}

// ---------------------------------------------------------------------------
// K1/K4: split-bf16 mma GEMM with register-prefetched B staging.
// ---------------------------------------------------------------------------
__global__ __launch_bounds__(256, 2) void k_gemm_mma(
    const float* __restrict__ W,
    const unsigned short* __restrict__ Xhi,
    const unsigned short* __restrict__ Xlo,
    float* __restrict__ Y, const float* __restrict__ bias,
    int hasBias, int Mtot)
{
    extern __shared__ uint32_t sm[];
    int tid = threadIdx.x;
    int lane = tid & 31, wid = tid >> 5;
    int g  = lane >> 2, tg = lane & 3;
    int warp_m = wid >> 2, warp_n = wid & 3;
    int m0 = blockIdx.y * 64;

    // CTA px range: 512 contiguous px -> b constant
    int gp0 = blockIdx.x * PXITER * NT;
    int b = gp0 / HWSZ, hw0base = gp0 % HWSZ;
    size_t xb = (size_t)b * KD * HWSZ;

    // ---- stage A (weights) once ----
    for (int u = tid; u < 64 * 48; u += 256) {
        int r = u / 48, q = u % 48;
        int k = q * 4;
        float4 v = *(const float4*)(W + (size_t)(m0 + r) * KD + k);
        uint32_t h0, l0, h1, l1;
        split2(v.x, v.y, h0, l0);
        split2(v.z, v.w, h1, l1);
        int ks = k >> 4, lh = (k >> 3) & 1, tgw = (k >> 1) & 3;
        int idx = ks * 512 + lh * 256 + r * 4 + tgw;
        sm[W_AHI + idx] = h0; sm[W_AHI + idx + 1] = h1;
        sm[W_ALO + idx] = l0; sm[W_ALO + idx + 1] = l1;
    }

    float bv[2][2] = {{0.f,0.f},{0.f,0.f}};
    if (hasBias) {
        #pragma unroll
        for (int mf = 0; mf < 2; mf++) {
            int row = m0 + warp_m * 32 + mf * 16 + g;
            bv[mf][0] = bias[row];
            bv[mf][1] = bias[row + 8];
        }
    }

    // B prefetch registers: 12 units x 4 words
    uint32_t pf[12][4];
    #define LOAD_B(ITER) do { \
        int hw_ = hw0base + (ITER) * NT; \
        _Pragma("unroll") \
        for (int u_ = 0; u_ < 12; u_++) { \
            int idx_ = tid + u_ * 256; \
            int kp_ = idx_ >> 5, pp_ = idx_ & 31; \
            const unsigned short* ph_ = Xhi + xb + (size_t)(kp_*2) * HWSZ + hw_ + pp_*2; \
            const unsigned short* pl_ = Xlo + xb + (size_t)(kp_*2) * HWSZ + hw_ + pp_*2; \
            pf[u_][0] = *(const uint32_t*)ph_; \
            pf[u_][1] = *(const uint32_t*)(ph_ + HWSZ); \
            pf[u_][2] = *(const uint32_t*)pl_; \
            pf[u_][3] = *(const uint32_t*)(pl_ + HWSZ); \
        } } while (0)

    LOAD_B(0);

    for (int it = 0; it < PXITER; ++it) {
        int hw0 = hw0base + it * NT;
        __syncthreads();   // prior iter smem reads done (covers A on it=0)

        // ---- STS prefetched B ----
        #pragma unroll
        for (int u = 0; u < 12; u++) {
            int idx = tid + u * 256;
            int kp = idx >> 5, pp = idx & 31;
            int px = pp * 2;
            int ks = kp >> 3, k2w = kp & 7;
            int sidx = (px >> 3) * BFRAG + ks * 64 + k2w * 8 + (px & 7);
            *(uint2*)&sm[W_BHI + sidx] =
                make_uint2(prmt(pf[u][0], pf[u][1], 0x5410), prmt(pf[u][0], pf[u][1], 0x7632));
            *(uint2*)&sm[W_BLO + sidx] =
                make_uint2(prmt(pf[u][2], pf[u][3], 0x5410), prmt(pf[u][2], pf[u][3], 0x7632));
        }
        __syncthreads();

        // issue next iteration's LDGs (overlap with mma below)
        if (it + 1 < PXITER) LOAD_B(it + 1);

        // ---- compute ----
        float c[2][2][4];
        #pragma unroll
        for (int mf = 0; mf < 2; mf++)
            #pragma unroll
            for (int nf = 0; nf < 2; nf++)
                #pragma unroll
                for (int i = 0; i < 4; i++) c[mf][nf][i] = 0.f;

        #pragma unroll
        for (int pass = 0; pass < 3; pass++) {
            const uint32_t* A = sm + (pass == 2 ? W_ALO : W_AHI);
            const uint32_t* B = sm + (pass == 1 ? W_BLO : W_BHI);
            #pragma unroll 4
            for (int ks = 0; ks < KSTEPS; ks++) {
                uint32_t af[2][4];
                #pragma unroll
                for (int mf = 0; mf < 2; mf++) {
                    int mb = warp_m * 32 + mf * 16;
                    const uint32_t* Ak = A + ks * 512;
                    af[mf][0] = Ak[(mb + g) * 4 + tg];
                    af[mf][1] = Ak[(mb + 8 + g) * 4 + tg];
                    af[mf][2] = Ak[256 + (mb + g) * 4 + tg];
                    af[mf][3] = Ak[256 + (mb + 8 + g) * 4 + tg];
                }
                uint32_t bfr[2][2];
                #pragma unroll
                for (int nf = 0; nf < 2; nf++) {
                    const uint32_t* Bk = B + (warp_n * 2 + nf) * BFRAG + ks * 64;
                    bfr[nf][0] = Bk[tg * 8 + g];
                    bfr[nf][1] = Bk[(tg + 4) * 8 + g];
                }
                #pragma unroll
                for (int mf = 0; mf < 2; mf++)
                    #pragma unroll
                    for (int nf = 0; nf < 2; nf++)
                        mma16816(c[mf][nf], af[mf], bfr[nf]);
            }
        }

        // ---- epilogue ----
        #pragma unroll
        for (int mf = 0; mf < 2; mf++) {
            int row0 = m0 + warp_m * 32 + mf * 16 + g;
            #pragma unroll
            for (int nf = 0; nf < 2; nf++) {
                int px = hw0 + (warp_n * 2 + nf) * 8 + tg * 2;
                float* d0 = Y + ((size_t)b * Mtot + row0) * HWSZ + px;
                float* d1 = Y + ((size_t)b * Mtot + row0 + 8) * HWSZ + px;
                *(float2*)d0 = make_float2(c[mf][nf][0] + bv[mf][0], c[mf][nf][1] + bv[mf][0]);
                *(float2*)d1 = make_float2(c[mf][nf][2] + bv[mf][1], c[mf][nf][3] + bv[mf][1]);
            }
        }
    }
    #undef LOAD_B
}

// ---------------------------------------------------------------------------
// K2: depthwise 3x3 (unchanged)
// ---------------------------------------------------------------------------
__global__ __launch_bounds__(128) void k_dw(const float* __restrict__ w_dw)
{
    int tid = threadIdx.x;
    int ty = tid >> 6, tx = tid & 63;
    int y  = blockIdx.x * 2 + ty;
    int ch = blockIdx.y;
    int b  = blockIdx.z;
    int x0 = tx << 2;

    const float* wk = w_dw + ch * 9;
    size_t base = ((size_t)b * C3 + ch) * HWSZ;
    const float* src = g_qkv + base;

    float4 o = make_float4(0.f, 0.f, 0.f, 0.f);

    #pragma unroll
    for (int dy = -1; dy <= 1; dy++) {
        int yy = y + dy;
        if (yy < 0 || yy >= HDIM) continue;
        const float* row = src + (size_t)yy * WDIM + x0;
        float4 m = *(const float4*)row;
        float lft = (x0 > 0)   ? row[-1] : 0.f;
        float rgt = (x0 < 252) ? row[4]  : 0.f;
        float wl = wk[(dy+1)*3], wc = wk[(dy+1)*3+1], wr = wk[(dy+1)*3+2];
        o.x += wl*lft + wc*m.x + wr*m.y;
        o.y += wl*m.x + wc*m.y + wr*m.z;
        o.z += wl*m.y + wc*m.z + wr*m.w;
        o.w += wl*m.z + wc*m.w + wr*rgt;
    }
    *(float4*)(g_dw + base + (size_t)y * WDIM + x0) = o;
}

// ---------------------------------------------------------------------------
// K3a: qk attention + out = attn.v  (writes fp32 out to scratch = g_qkv)
// smem 29.6KB -> 6+ blocks/SM
// ---------------------------------------------------------------------------
__global__ __launch_bounds__(128, 6) void k_attn_av(
    const float* __restrict__ temp, float* __restrict__ g_out)
{
    __shared__ float sq[32 * 66];
    __shared__ float sk[32 * 66];
    __shared__ float sv[32 * 66];
    __shared__ float satt[32 * 33];

    int tid  = threadIdx.x;
    int wi   = blockIdx.x;
    int head = blockIdx.y;
    int b  = wi >> 10;
    int r  = wi & 1023;
    int h1 = r >> 5, w1 = r & 31;

    float tscale = temp[head];

    // load q/k/v
    for (int i = tid; i < 1536; i += 128) {
        int z = i / 512;
        int rr = i - z * 512;
        int c  = rr >> 4;
        int q8 = rr & 15;
        int ty = q8 >> 1, half = q8 & 1;
        const float* gp = g_dw +
            (((size_t)(b * C3 + z * CDIM + head * CHD + c)) * HDIM + (h1*8 + ty)) * WDIM
            + w1 * 8 + half * 4;
        float4 v = *(const float4*)gp;
        float* s = (z == 0 ? sq : (z == 1 ? sk : sv)) + c * 66 + ty * 8 + half * 4;
        s[0] = v.x; s[1] = v.y; s[2] = v.z; s[3] = v.w;
    }
    __syncthreads();

    // l2norm q, k
    if (tid < 64) {
        float* row = (tid < 32) ? (sq + tid * 66) : (sk + (tid - 32) * 66);
        u64 s2 = 0ull;
        #pragma unroll
        for (int t = 0; t < 64; t += 2) {
            u64 v = *(const u64*)(row + t);
            fma2(s2, v, v);
        }
        float2 sp = up2(s2);
        float n = fmaxf(sqrtf(sp.x + sp.y), 1e-12f);
        u64 inv = pk1(1.f / n);
        #pragma unroll
        for (int t = 0; t < 64; t += 2) {
            u64 v = *(const u64*)(row + t);
            mul2(v, v, inv);
            *(u64*)(row + t) = v;
        }
    }
    __syncthreads();

    // qk: 2c x 4d per thread
    {
        int cb = tid >> 3, db = tid & 7;
        int c0 = cb * 2, d0 = db * 4;
        u64 acc[2][4];
        #pragma unroll
        for (int i = 0; i < 2; i++)
            #pragma unroll
            for (int j = 0; j < 4; j++) acc[i][j] = 0ull;
        const float* q0 = sq + c0 * 66;
        const float* k0 = sk + d0 * 66;
        #pragma unroll
        for (int t = 0; t < 64; t += 2) {
            u64 qa = *(const u64*)(q0 + t);
            u64 qb = *(const u64*)(q0 + 66 + t);
            u64 k_0 = *(const u64*)(k0 + t);
            u64 k_1 = *(const u64*)(k0 + 66 + t);
            u64 k_2 = *(const u64*)(k0 + 132 + t);
            u64 k_3 = *(const u64*)(k0 + 198 + t);
            fma2(acc[0][0], qa, k_0); fma2(acc[0][1], qa, k_1);
            fma2(acc[0][2], qa, k_2); fma2(acc[0][3], qa, k_3);
            fma2(acc[1][0], qb, k_0); fma2(acc[1][1], qb, k_1);
            fma2(acc[1][2], qb, k_2); fma2(acc[1][3], qb, k_3);
        }
        #pragma unroll
        for (int i = 0; i < 2; i++)
            #pragma unroll
            for (int j = 0; j < 4; j++) {
                float2 sp = up2(acc[i][j]);
                satt[(c0 + i) * 33 + d0 + j] = (sp.x + sp.y) * tscale;
            }
    }
    __syncthreads();

    // softmax
    if (tid < 32) {
        float* rr = satt + tid * 33;
        float mx = rr[0];
        #pragma unroll
        for (int d = 1; d < 32; d++) mx = fmaxf(mx, rr[d]);
        float s = 0.f;
        #pragma unroll
        for (int d = 0; d < 32; d++) { float ev = __expf(rr[d] - mx); rr[d] = ev; s += ev; }
        float inv = 1.f / s;
        #pragma unroll
        for (int d = 0; d < 32; d++) rr[d] *= inv;
    }
    __syncthreads();

    // out = attn.v : 4c x 4t per thread, write fp32 float4
    {
        int cb = tid >> 4, tb = tid & 15;
        int c0 = cb * 4, t0 = tb * 4;
        u64 oacc[4][2];
        #pragma unroll
        for (int i = 0; i < 4; i++) { oacc[i][0] = 0ull; oacc[i][1] = 0ull; }
        #pragma unroll 8
        for (int d = 0; d < 32; d++) {
            u64 v0 = *(const u64*)(sv + d * 66 + t0);
            u64 v1 = *(const u64*)(sv + d * 66 + t0 + 2);
            #pragma unroll
            for (int i = 0; i < 4; i++) {
                u64 ap = pk1(satt[(c0 + i) * 33 + d]);
                fma2(oacc[i][0], ap, v0);
                fma2(oacc[i][1], ap, v1);
            }
        }
        #pragma unroll
        for (int i = 0; i < 4; i++) {
            float2 o0 = up2(oacc[i][0]), o1 = up2(oacc[i][1]);
            size_t base = (((size_t)(b * CDIM + head * CHD + c0 + i)) * HDIM
                           + (h1*8 + (t0 >> 3))) * WDIM + w1 * 8 + (t0 & 7);
            *(float4*)(g_out + base) = make_float4(o0.x, o0.y, o1.x, o1.y);
        }
    }
}

// ---------------------------------------------------------------------------
// K3b: gate = GELU(v @ mlp^T + b); result = out * gate, split bf16 stores.
// smem 25.8KB -> 6+ blocks/SM
// ---------------------------------------------------------------------------
__global__ __launch_bounds__(128, 6) void k_gate(
    const float* __restrict__ mlp_w,
    const float* __restrict__ mlp_b,
    const float* __restrict__ g_out)
{
    __shared__ float sv[32 * 66];
    __shared__ float sml[64 * 66];   // transposed: sml[x*66+t] = mlp_w[t*64+x]
    __shared__ float sb[64];

    int tid  = threadIdx.x;
    int wi   = blockIdx.x;
    int head = blockIdx.y;
    int b  = wi >> 10;
    int r  = wi & 1023;
    int h1 = r >> 5, w1 = r & 31;

    // load v (z=2 section of g_dw)
    for (int i = tid; i < 512; i += 128) {
        int c  = i >> 4;
        int q8 = i & 15;
        int ty = q8 >> 1, half = q8 & 1;
        const float* gp = g_dw +
            (((size_t)(b * C3 + 2 * CDIM + head * CHD + c)) * HDIM + (h1*8 + ty)) * WDIM
            + w1 * 8 + half * 4;
        float4 v = *(const float4*)gp;
        float* s = sv + c * 66 + ty * 8 + half * 4;
        s[0] = v.x; s[1] = v.y; s[2] = v.z; s[3] = v.w;
    }
    for (int i = tid; i < 4096; i += 128)
        sml[(i & 63) * 66 + (i >> 6)] = mlp_w[i];
    if (tid < 64) sb[tid] = mlp_b[tid];
    __syncthreads();

    // gate: 4c x 4t per thread
    int cb = tid >> 4, tb = tid & 15;
    int c0 = cb * 4, t0 = tb * 4;

    u64 gacc[4][2];
    #pragma unroll
    for (int i = 0; i < 4; i++) { gacc[i][0] = 0ull; gacc[i][1] = 0ull; }
    #pragma unroll 8
    for (int x = 0; x < 64; x++) {
        u64 m0 = *(const u64*)(sml + x * 66 + t0);
        u64 m1 = *(const u64*)(sml + x * 66 + t0 + 2);
        #pragma unroll
        for (int i = 0; i < 4; i++) {
            u64 vp = pk1(sv[(c0 + i) * 66 + x]);
            fma2(gacc[i][0], vp, m0);
            fma2(gacc[i][1], vp, m1);
        }
    }

    float b0 = sb[t0], b1 = sb[t0+1], b2 = sb[t0+2], b3 = sb[t0+3];
    #pragma unroll
    for (int i = 0; i < 4; i++) {
        int c = c0 + i;
        size_t base = (((size_t)(b * CDIM + head * CHD + c)) * HDIM
                       + (h1*8 + (t0 >> 3))) * WDIM + w1 * 8 + (t0 & 7);
        float4 ov = *(const float4*)(g_out + base);
        float2 g0 = up2(gacc[i][0]), g1 = up2(gacc[i][1]);
        float gv0 = g0.x + b0, gv1 = g0.y + b1, gv2 = g1.x + b2, gv3 = g1.y + b3;
        const float is2 = 0.70710678118654752f;
        float r0 = ov.x * (0.5f * gv0 * (1.f + erff(gv0 * is2)));
        float r1 = ov.y * (0.5f * gv1 * (1.f + erff(gv1 * is2)));
        float r2 = ov.z * (0.5f * gv2 * (1.f + erff(gv2 * is2)));
        float r3 = ov.w * (0.5f * gv3 * (1.f + erff(gv3 * is2)));
        uint32_t h0_, l0_, h1_, l1_;
        split2(r0, r1, h0_, l0_);
        split2(r2, r3, h1_, l1_);
        *(uint32_t*)(g_thi + base)     = h0_;
        *(uint32_t*)(g_thi + base + 2) = h1_;
        *(uint32_t*)(g_tlo + base)     = l0_;
        *(uint32_t*)(g_tlo + base + 2) = l1_;
    }
}

// ---------------------------------------------------------------------------
extern "C" void kernel_launch(void* const* d_in, const int* in_sizes, int n_in,
                              void* d_out, int out_size)
{
    const float* x      = (const float*)d_in[0];
    const float* w_qkv  = (const float*)d_in[1];
    const float* w_dw   = (const float*)d_in[2];
    const float* temp   = (const float*)d_in[3];
    const float* mlp_w  = (const float*)d_in[4];
    const float* mlp_b  = (const float*)d_in[5];
    const float* proj_w = (const float*)d_in[6];
    const float* proj_b = (const float*)d_in[7];
    float* out = (float*)d_out;
    (void)in_sizes; (void)n_in; (void)out_size;

    float *p_qkv;
    unsigned short *p_xhi, *p_xlo, *p_thi, *p_tlo;
    cudaGetSymbolAddress((void**)&p_qkv, g_qkv);
    cudaGetSymbolAddress((void**)&p_xhi, g_xhi);
    cudaGetSymbolAddress((void**)&p_xlo, g_xlo);
    cudaGetSymbolAddress((void**)&p_thi, g_thi);
    cudaGetSymbolAddress((void**)&p_tlo, g_tlo);

    cudaFuncSetAttribute(k_gemm_mma, cudaFuncAttributeMaxDynamicSharedMemorySize,
                         SMEM_BYTES);

    // K0: split x into bf16 hi/lo
    k_split<<<(BATCH*KD*HWSZ)/(256*4), 256>>>(x, p_xhi, p_xlo);

    // K1: qkv = W_qkv @ x
    k_gemm_mma<<<dim3(BATCH*HWSZ/NT/PXITER, C3/64), 256, SMEM_BYTES>>>(
        w_qkv, p_xhi, p_xlo, p_qkv, nullptr, 0, C3);

    // K2: depthwise 3x3
    k_dw<<<dim3(HDIM/2, C3, BATCH), 128>>>(w_dw);

    // K3a: attention + out (g_qkv dead after k_dw -> reuse as out scratch)
    k_attn_av<<<dim3(NWIN, HEADS), 128>>>(temp, p_qkv);

    // K3b: gate + multiply + split store
    k_gate<<<dim3(NWIN, HEADS), 128>>>(mlp_w, mlp_b, p_qkv);

    // K4: projection + bias -> d_out
    k_gemm_mma<<<dim3(BATCH*HWSZ/NT/PXITER, CDIM/64), 256, SMEM_BYTES>>>(
        proj_w, p_thi, p_tlo, out, proj_b, 1, CDIM);
}